// round 4
// baseline (speedup 1.0000x reference)
#include <cuda_runtime.h>
#include <cuda_bf16.h>
#include <cstdint>

#define NPTS 4096
#define ZSTR 52
#define QSCALE 24000.0f
#define INV_RENORM (1.0f / 1.004096f)

// ---- scratch (device globals; no allocation allowed) ----
__device__ __align__(16) float g_z[4 * NPTS * ZSTR];
__device__ __align__(16) float g_sq[4 * NPTS];

// ===========================================================================
// Kernel 1: MLP 256 -> 128 -> 64 -> 50 (+ squared norms)
// 16 rows per CTA, 256 threads, grid = 16384/16 = 1024
// ===========================================================================
__global__ __launch_bounds__(256) void mlp_kernel(
    const float* __restrict__ emb,
    const float* __restrict__ W1, const float* __restrict__ b1,
    const float* __restrict__ W2, const float* __restrict__ b2,
    const float* __restrict__ W3, const float* __restrict__ b3)
{
    __shared__ float E_s [16][256];
    __shared__ float h1_s[16][128];
    __shared__ float h2_s[16][64];
    __shared__ float z_s [16][ZSTR];

    const int t = threadIdx.x;
    const size_t rowbase = (size_t)blockIdx.x * 16;

    // load 16x256 embedding tile
    {
        const float4* src = (const float4*)(emb + rowbase * 256);
        float4* dst = (float4*)&E_s[0][0];
        #pragma unroll
        for (int i = 0; i < 4; i++) dst[t + i * 256] = src[t + i * 256];
    }
    __syncthreads();

    // layer 1: 256 -> 128, relu.  f = t&127, two row groups of 8.
    {
        const int f = t & 127, rg = (t >> 7) * 8;
        float acc[8];
        #pragma unroll
        for (int r = 0; r < 8; r++) acc[r] = 0.f;
        const float* w = W1 + f;
        #pragma unroll 2
        for (int d = 0; d < 256; d += 4) {
            float w0 = w[(d + 0) * 128], w1 = w[(d + 1) * 128];
            float w2 = w[(d + 2) * 128], w3 = w[(d + 3) * 128];
            #pragma unroll
            for (int r = 0; r < 8; r++) {
                float4 e = *(const float4*)&E_s[rg + r][d];
                acc[r] = fmaf(e.x, w0, acc[r]); acc[r] = fmaf(e.y, w1, acc[r]);
                acc[r] = fmaf(e.z, w2, acc[r]); acc[r] = fmaf(e.w, w3, acc[r]);
            }
        }
        const float bb = b1[f];
        #pragma unroll
        for (int r = 0; r < 8; r++) h1_s[rg + r][f] = fmaxf(acc[r] + bb, 0.f);
    }
    __syncthreads();

    // layer 2: 128 -> 64, relu.  f = t&63, four row groups of 4.
    {
        const int f = t & 63, rg = (t >> 6) * 4;
        float acc[4] = {0.f, 0.f, 0.f, 0.f};
        const float* w = W2 + f;
        #pragma unroll 2
        for (int d = 0; d < 128; d += 4) {
            float w0 = w[(d + 0) * 64], w1 = w[(d + 1) * 64];
            float w2 = w[(d + 2) * 64], w3 = w[(d + 3) * 64];
            #pragma unroll
            for (int r = 0; r < 4; r++) {
                float4 e = *(const float4*)&h1_s[rg + r][d];
                acc[r] = fmaf(e.x, w0, acc[r]); acc[r] = fmaf(e.y, w1, acc[r]);
                acc[r] = fmaf(e.z, w2, acc[r]); acc[r] = fmaf(e.w, w3, acc[r]);
            }
        }
        const float bb = b2[f];
        #pragma unroll
        for (int r = 0; r < 4; r++) h2_s[rg + r][f] = fmaxf(acc[r] + bb, 0.f);
    }
    __syncthreads();

    // layer 3: 64 -> 50 (no relu)
    {
        const int f = t & 63, rg = (t >> 6) * 4;
        if (f < 50) {
            float acc[4] = {0.f, 0.f, 0.f, 0.f};
            const float* w = W3 + f;
            #pragma unroll
            for (int d = 0; d < 64; d += 4) {
                float w0 = w[(d + 0) * 50], w1 = w[(d + 1) * 50];
                float w2 = w[(d + 2) * 50], w3 = w[(d + 3) * 50];
                #pragma unroll
                for (int r = 0; r < 4; r++) {
                    float4 e = *(const float4*)&h2_s[rg + r][d];
                    acc[r] = fmaf(e.x, w0, acc[r]); acc[r] = fmaf(e.y, w1, acc[r]);
                    acc[r] = fmaf(e.z, w2, acc[r]); acc[r] = fmaf(e.w, w3, acc[r]);
                }
            }
            const float bb = b3[f];
            #pragma unroll
            for (int r = 0; r < 4; r++) z_s[rg + r][f] = acc[r] + bb;
        }
    }
    // zero the 2-element pad so scratch is clean
    if (t < 16) { z_s[t][50] = 0.f; z_s[t][51] = 0.f; }
    __syncthreads();

    // write z (16 rows x 13 float4)
    if (t < 208) {
        const int row = t / 13, i4 = t % 13;
        ((float4*)(g_z + (rowbase + row) * ZSTR))[i4] = *(const float4*)&z_s[row][i4 * 4];
    }
    // squared norms (sequential, deterministic)
    if (t < 16) {
        float s2 = 0.f;
        #pragma unroll
        for (int k = 0; k < 50; k++) s2 = fmaf(z_s[t][k], z_s[t][k], s2);
        g_sq[rowbase + t] = s2;
    }
}

// ===========================================================================
// Kernel 2: gram + fused softmax/renorm.
// Each CTA: one batch b, 16 rows, all 4096 cols. 256 threads.
// Dynamic smem layout (bytes):
//   [0,        131072)  numer  : u16[16][4096]
//   [131072,   182272)  zcolT  : f32[50][256]
//   [182272,   185472)  zrowT  : f32[50][16]
//   [185472,   186496)  sqc    : f32[256]
//   [186496,   186560)  sqr    : f32[16]
//   [186560,   186624)  rowsum : i32[16]
//   [186624,   186688)  scale  : f32[16]
// ===========================================================================
#define GRAM_SMEM 186688

__global__ __launch_bounds__(256) void gram_kernel(float* __restrict__ out)
{
    extern __shared__ char sm[];
    unsigned short* numer  = (unsigned short*)sm;
    float*          zcolT  = (float*)(sm + 131072);
    float*          zrowT  = (float*)(sm + 182272);
    float*          sqc    = (float*)(sm + 185472);
    float*          sqr    = (float*)(sm + 186496);
    int*            rowsum = (int*)  (sm + 186560);
    float*          scale_s= (float*)(sm + 186624);

    const int t  = threadIdx.x;
    const int b  = blockIdx.x >> 8;
    const int r0 = (blockIdx.x & 255) * 16;
    const int rg = t >> 6;   // row group: rows rg*4 .. rg*4+3 (uniform per warp)
    const int cg = t & 63;   // col group: cols cg*4 .. cg*4+3

    // load zrowT (transposed), sqr, init rowsum
    if (t < 208) {
        const int row = t / 13, i4 = t % 13;
        float4 v = ((const float4*)(g_z + ((size_t)b * NPTS + r0 + row) * ZSTR))[i4];
        const int k = i4 * 4;
        zrowT[k * 16 + row] = v.x;
        if (k + 1 < 50) zrowT[(k + 1) * 16 + row] = v.y;
        if (k + 2 < 50) zrowT[(k + 2) * 16 + row] = v.z;
        if (k + 3 < 50) zrowT[(k + 3) * 16 + row] = v.w;
    }
    if (t < 16) { sqr[t] = g_sq[(size_t)b * NPTS + r0 + t]; rowsum[t] = 0; }
    __syncthreads();

    int rs[4] = {0, 0, 0, 0};

    for (int tile = 0; tile < 16; tile++) {
        const int col0 = tile * 256;
        // load zcolT (transposed): thread t owns z-row (col0+t)
        {
            const float4* src = (const float4*)(g_z + ((size_t)b * NPTS + col0 + t) * ZSTR);
            #pragma unroll
            for (int i4 = 0; i4 < 13; i4++) {
                float4 v = src[i4];
                const int k = i4 * 4;
                zcolT[k * 256 + t] = v.x;
                zcolT[(k + 1) * 256 + t] = v.y;
                if (k + 2 < 50) zcolT[(k + 2) * 256 + t] = v.z;
                if (k + 3 < 50) zcolT[(k + 3) * 256 + t] = v.w;
            }
            sqc[t] = g_sq[(size_t)b * NPTS + col0 + t];
        }
        __syncthreads();

        float acc[4][4];
        #pragma unroll
        for (int r = 0; r < 4; r++)
            #pragma unroll
            for (int c = 0; c < 4; c++) acc[r][c] = 0.f;

        #pragma unroll 2
        for (int k = 0; k < 50; k++) {
            float4 a = *(const float4*)&zrowT[k * 16 + rg * 4];   // warp-broadcast
            float4 cc = *(const float4*)&zcolT[k * 256 + cg * 4]; // conflict-free
            float av[4] = {a.x, a.y, a.z, a.w};
            float cv[4] = {cc.x, cc.y, cc.z, cc.w};
            #pragma unroll
            for (int r = 0; r < 4; r++)
                #pragma unroll
                for (int c = 0; c < 4; c++)
                    acc[r][c] = fmaf(av[r], cv[c], acc[r][c]);
        }

        #pragma unroll
        for (int r = 0; r < 4; r++) {
            const float sr = sqr[rg * 4 + r];
            ushort4 uu;
            unsigned short* up = &uu.x;
            #pragma unroll
            for (int c = 0; c < 4; c++) {
                float dist = fmaxf(sr + sqc[cg * 4 + c] - 2.f * acc[r][c], 0.f);
                float kern = __expf(-0.5f * dist);
                float num  = __expf(kern);           // numerator of softmax(kernel), max = e
                unsigned u = __float2uint_rn(num * QSCALE);
                rs[r] += (int)u;
                up[c] = (unsigned short)u;
            }
            *(ushort4*)&numer[(size_t)(rg * 4 + r) * NPTS + col0 + cg * 4] = uu;
        }
        __syncthreads();
    }

    // deterministic integer row sums
    #pragma unroll
    for (int r = 0; r < 4; r++) atomicAdd(&rowsum[rg * 4 + r], rs[r]);
    __syncthreads();
    if (t < 16) scale_s[t] = (1.0f / (float)rowsum[t]) * INV_RENORM;
    __syncthreads();

    // rescale + write: out = (u/S + 1e-6) / (1 + N*1e-6)
    const float bias = 1e-6f * INV_RENORM;
    float* outb = out + ((size_t)b * NPTS + r0) * NPTS;
    #pragma unroll 4
    for (int i = 0; i < 64; i++) {
        const int idx = i * 256 + t;
        const int row = idx >> 10, c4 = idx & 1023;
        uint2 w = *(const uint2*)(numer + ((size_t)row << 12) + (c4 << 2));
        const float s = scale_s[row];
        float4 o;
        o.x = fmaf((float)(w.x & 0xFFFFu), s, bias);
        o.y = fmaf((float)(w.x >> 16),     s, bias);
        o.z = fmaf((float)(w.y & 0xFFFFu), s, bias);
        o.w = fmaf((float)(w.y >> 16),     s, bias);
        ((float4*)(outb + (size_t)row * NPTS))[c4] = o;
    }
}

// ===========================================================================
extern "C" void kernel_launch(void* const* d_in, const int* in_sizes, int n_in,
                              void* d_out, int out_size)
{
    const float* emb = (const float*)d_in[0];
    const float* W1  = (const float*)d_in[1];
    const float* b1  = (const float*)d_in[2];
    const float* W2  = (const float*)d_in[3];
    const float* b2  = (const float*)d_in[4];
    const float* W3  = (const float*)d_in[5];
    const float* b3  = (const float*)d_in[6];
    float* out = (float*)d_out;

    cudaFuncSetAttribute(gram_kernel, cudaFuncAttributeMaxDynamicSharedMemorySize, GRAM_SMEM);

    mlp_kernel<<<1024, 256>>>(emb, W1, b1, W2, b2, W3, b3);
    gram_kernel<<<1024, 256, GRAM_SMEM>>>(out);
}

// round 5
// speedup vs baseline: 1.4594x; 1.4594x over previous
#include <cuda_runtime.h>
#include <cuda_bf16.h>
#include <cstdint>

#define NPTS 4096
#define NROWS_TOT 16384
#define QSCALE 24000.0f
#define INV_RENORM (1.0f / 1.004096f)

// smem strides (elements)
#define ASTR 72
#define BSTR 72
#define NSTR 264

// ---- device-global scratch (no allocation allowed) ----
__device__ __align__(16) unsigned short g_zhi[NROWS_TOT * 64];
__device__ __align__(16) unsigned short g_zlo[NROWS_TOT * 64];
__device__ __align__(16) float          g_sq [NROWS_TOT];
__device__ __align__(16) unsigned short g_num[(size_t)NROWS_TOT * NPTS]; // 134MB
__device__ __align__(16) float          g_scale[NROWS_TOT];

// ===========================================================================
// Kernel 1: MLP 256 -> 128 -> 64 -> 50, outputs bf16 split (hi/lo, K padded
// to 64) + fp32 squared norms.  16 rows/CTA, 256 threads, grid 1024.
// ===========================================================================
__global__ __launch_bounds__(256) void mlp_kernel(
    const float* __restrict__ emb,
    const float* __restrict__ W1, const float* __restrict__ b1,
    const float* __restrict__ W2, const float* __restrict__ b2,
    const float* __restrict__ W3, const float* __restrict__ b3)
{
    __shared__ float E_s [16][256];
    __shared__ float h1_s[16][128];
    __shared__ float h2_s[16][64];
    __shared__ float z_s [16][52];

    const int t = threadIdx.x;
    const size_t rowbase = (size_t)blockIdx.x * 16;

    {
        const float4* src = (const float4*)(emb + rowbase * 256);
        float4* dst = (float4*)&E_s[0][0];
        #pragma unroll
        for (int i = 0; i < 4; i++) dst[t + i * 256] = src[t + i * 256];
    }
    __syncthreads();

    // layer 1: 256 -> 128, relu
    {
        const int f = t & 127, rg = (t >> 7) * 8;
        float acc[8];
        #pragma unroll
        for (int r = 0; r < 8; r++) acc[r] = 0.f;
        const float* w = W1 + f;
        #pragma unroll 2
        for (int d = 0; d < 256; d += 4) {
            float w0 = w[(d + 0) * 128], w1 = w[(d + 1) * 128];
            float w2 = w[(d + 2) * 128], w3 = w[(d + 3) * 128];
            #pragma unroll
            for (int r = 0; r < 8; r++) {
                float4 e = *(const float4*)&E_s[rg + r][d];
                acc[r] = fmaf(e.x, w0, acc[r]); acc[r] = fmaf(e.y, w1, acc[r]);
                acc[r] = fmaf(e.z, w2, acc[r]); acc[r] = fmaf(e.w, w3, acc[r]);
            }
        }
        const float bb = b1[f];
        #pragma unroll
        for (int r = 0; r < 8; r++) h1_s[rg + r][f] = fmaxf(acc[r] + bb, 0.f);
    }
    __syncthreads();

    // layer 2: 128 -> 64, relu
    {
        const int f = t & 63, rg = (t >> 6) * 4;
        float acc[4] = {0.f, 0.f, 0.f, 0.f};
        const float* w = W2 + f;
        #pragma unroll 2
        for (int d = 0; d < 128; d += 4) {
            float w0 = w[(d + 0) * 64], w1 = w[(d + 1) * 64];
            float w2 = w[(d + 2) * 64], w3 = w[(d + 3) * 64];
            #pragma unroll
            for (int r = 0; r < 4; r++) {
                float4 e = *(const float4*)&h1_s[rg + r][d];
                acc[r] = fmaf(e.x, w0, acc[r]); acc[r] = fmaf(e.y, w1, acc[r]);
                acc[r] = fmaf(e.z, w2, acc[r]); acc[r] = fmaf(e.w, w3, acc[r]);
            }
        }
        const float bb = b2[f];
        #pragma unroll
        for (int r = 0; r < 4; r++) h2_s[rg + r][f] = fmaxf(acc[r] + bb, 0.f);
    }
    __syncthreads();

    // layer 3: 64 -> 50
    {
        const int f = t & 63, rg = (t >> 6) * 4;
        if (f < 50) {
            float acc[4] = {0.f, 0.f, 0.f, 0.f};
            const float* w = W3 + f;
            #pragma unroll
            for (int d = 0; d < 64; d += 4) {
                float w0 = w[(d + 0) * 50], w1 = w[(d + 1) * 50];
                float w2 = w[(d + 2) * 50], w3 = w[(d + 3) * 50];
                #pragma unroll
                for (int r = 0; r < 4; r++) {
                    float4 e = *(const float4*)&h2_s[rg + r][d];
                    acc[r] = fmaf(e.x, w0, acc[r]); acc[r] = fmaf(e.y, w1, acc[r]);
                    acc[r] = fmaf(e.z, w2, acc[r]); acc[r] = fmaf(e.w, w3, acc[r]);
                }
            }
            const float bb = b3[f];
            #pragma unroll
            for (int r = 0; r < 4; r++) z_s[rg + r][f] = acc[r] + bb;
        }
    }
    __syncthreads();

    // bf16 split write: row = t>>4, k0 = (t&15)*4, pad K 50->64 with zeros
    {
        const int row = t >> 4, k0 = (t & 15) * 4;
        ushort4 hi4, lo4;
        unsigned short* hp = &hi4.x;
        unsigned short* lp = &lo4.x;
        #pragma unroll
        for (int j = 0; j < 4; j++) {
            const int k = k0 + j;
            float v = (k < 50) ? z_s[row][k] : 0.f;
            __nv_bfloat16 h = __float2bfloat16(v);
            float hf = __bfloat162float(h);
            __nv_bfloat16 l = __float2bfloat16(v - hf);
            hp[j] = __bfloat16_as_ushort(h);
            lp[j] = __bfloat16_as_ushort(l);
        }
        const size_t base = ((rowbase + row) << 6) + k0;
        *(ushort4*)(g_zhi + base) = hi4;
        *(ushort4*)(g_zlo + base) = lo4;
    }
    // squared norms (sequential, deterministic)
    if (t < 16) {
        float s2 = 0.f;
        #pragma unroll
        for (int k = 0; k < 50; k++) s2 = fmaf(z_s[t][k], z_s[t][k], s2);
        g_sq[rowbase + t] = s2;
    }
}

// ===========================================================================
// Kernel 2: tensor-core gram + exp(exp) + u16 quantize + exact int rowsums.
// CTA = 32 rows x 4096 cols, 256 threads (8 warps), warp w owns 32 cols/tile.
// bf16 split: dot = hi.hi + hi.lo + lo.hi.
// smem layout (bytes):
//   B_HI 0       : [256][72] bf16 = 36864
//   B_LO 36864   : [256][72] bf16 = 36864
//   A_HI 73728   : [32][72]  bf16 = 4608
//   A_LO 78336   : [32][72]  bf16 = 4608
//   NUM  82944   : [32][264] u16  = 16896
//   SQC  99840   : [256] f32      = 1024
//   SQR  100864  : [32] f32       = 128
//   RSUM 100992  : [32] int       = 128
// ===========================================================================
#define OFF_BHI 0
#define OFF_BLO 36864
#define OFF_AHI 73728
#define OFF_ALO 78336
#define OFF_NUM 82944
#define OFF_SQC 99840
#define OFF_SQR 100864
#define OFF_RSUM 100992
#define GRAM_SMEM 101120

__device__ __forceinline__ void ldsm_x4(uint32_t addr, uint32_t& r0, uint32_t& r1,
                                        uint32_t& r2, uint32_t& r3) {
    asm volatile("ldmatrix.sync.aligned.m8n8.x4.shared.b16 {%0,%1,%2,%3}, [%4];"
                 : "=r"(r0), "=r"(r1), "=r"(r2), "=r"(r3) : "r"(addr));
}
__device__ __forceinline__ void ldsm_x2(uint32_t addr, uint32_t& r0, uint32_t& r1) {
    asm volatile("ldmatrix.sync.aligned.m8n8.x2.shared.b16 {%0,%1}, [%2];"
                 : "=r"(r0), "=r"(r1) : "r"(addr));
}
__device__ __forceinline__ void mma_bf16(float* d, const uint32_t* a, const uint32_t* b) {
    asm volatile(
        "mma.sync.aligned.m16n8k16.row.col.f32.bf16.bf16.f32 "
        "{%0,%1,%2,%3},{%4,%5,%6,%7},{%8,%9},{%0,%1,%2,%3};"
        : "+f"(d[0]), "+f"(d[1]), "+f"(d[2]), "+f"(d[3])
        : "r"(a[0]), "r"(a[1]), "r"(a[2]), "r"(a[3]), "r"(b[0]), "r"(b[1]));
}

__device__ __forceinline__ unsigned quant_el(float sr, float sc, float dot) {
    float dist = fmaxf(sr + sc - 2.f * dot, 0.f);
    float num = __expf(__expf(-0.5f * dist));
    return __float2uint_rn(num * QSCALE);
}

__global__ __launch_bounds__(256) void gram_kernel()
{
    extern __shared__ char sm[];
    uint32_t smu;
    asm("{ .reg .u64 tt; cvta.to.shared.u64 tt, %1; cvt.u32.u64 %0, tt; }"
        : "=r"(smu) : "l"(sm));

    float* sq_c  = (float*)(sm + OFF_SQC);
    float* sq_r  = (float*)(sm + OFF_SQR);
    int*   rsum  = (int*)  (sm + OFF_RSUM);

    const int t    = threadIdx.x;
    const int lane = t & 31, warp = t >> 5;
    const int b    = blockIdx.x >> 7;
    const int r0   = (blockIdx.x & 127) * 32;
    const int gr   = lane >> 2;

    // ---- load A (32 rows, hi+lo) + sq_r + init rowsum ----
    {
        const int row = t >> 3, seg = t & 7;
        const size_t src = ((size_t)(b * NPTS + r0 + row) << 6) + seg * 8;
        const int dsto = (row * ASTR + seg * 8) * 2;
        *(uint4*)(sm + OFF_AHI + dsto) = *(const uint4*)(g_zhi + src);
        *(uint4*)(sm + OFF_ALO + dsto) = *(const uint4*)(g_zlo + src);
    }
    if (t < 32) { sq_r[t] = g_sq[b * NPTS + r0 + t]; rsum[t] = 0; }

    // precomputed ldmatrix lane offsets
    const int a_lr = (lane & 7) + ((lane >> 3) & 1) * 8;
    const int a_lc = (lane >> 4) * 8;
    const int b_lr = warp * 32 + (lane & 7);
    const int b_lc = ((lane >> 3) & 1) * 8;

    for (int tile = 0; tile < 16; tile++) {
        const int col0 = tile * 256;
        __syncthreads();   // prev tile's mma + numer copy-out fully done

        // ---- load B tile (256 cols, hi+lo) + sq_c ----
        #pragma unroll
        for (int i = 0; i < 8; i++) {
            const int idx = t + i * 256;
            const int row = idx >> 3, seg = idx & 7;
            const size_t src = ((size_t)(b * NPTS + col0 + row) << 6) + seg * 8;
            const int dsto = (row * BSTR + seg * 8) * 2;
            *(uint4*)(sm + OFF_BHI + dsto) = *(const uint4*)(g_zhi + src);
            *(uint4*)(sm + OFF_BLO + dsto) = *(const uint4*)(g_zlo + src);
        }
        sq_c[t] = g_sq[b * NPTS + col0 + t];
        __syncthreads();

        // ---- mma: 3 split terms x 4 k-steps x (2 m-sub x 4 n-sub) ----
        float acc[2][4][4];
        #pragma unroll
        for (int ms = 0; ms < 2; ms++)
            #pragma unroll
            for (int ns = 0; ns < 4; ns++)
                #pragma unroll
                for (int q = 0; q < 4; q++) acc[ms][ns][q] = 0.f;

        #pragma unroll
        for (int term = 0; term < 3; term++) {
            const uint32_t abase = smu + ((term == 2) ? OFF_ALO : OFF_AHI);
            const uint32_t bbase = smu + ((term == 1) ? OFF_BLO : OFF_BHI);
            #pragma unroll
            for (int ks = 0; ks < 4; ks++) {
                const int kk = ks * 16;
                uint32_t af[2][4];
                #pragma unroll
                for (int ms = 0; ms < 2; ms++) {
                    uint32_t addr = abase +
                        (((ms * 16 + a_lr) * ASTR) + kk + a_lc) * 2;
                    ldsm_x4(addr, af[ms][0], af[ms][1], af[ms][2], af[ms][3]);
                }
                #pragma unroll
                for (int ns = 0; ns < 4; ns++) {
                    uint32_t bf[2];
                    uint32_t addr = bbase +
                        (((b_lr + ns * 8) * BSTR) + kk + b_lc) * 2;
                    ldsm_x2(addr, bf[0], bf[1]);
                    mma_bf16(acc[0][ns], af[0], bf);
                    mma_bf16(acc[1][ns], af[1], bf);
                }
            }
        }

        // ---- epilogue: dist -> exp(exp) -> u16, stage to smem ----
        #pragma unroll
        for (int ms = 0; ms < 2; ms++) {
            const int ra = ms * 16 + gr;
            const float sra = sq_r[ra], srb = sq_r[ra + 8];
            #pragma unroll
            for (int ns = 0; ns < 4; ns++) {
                const int col = warp * 32 + ns * 8 + (lane & 3) * 2;
                const float sc0 = sq_c[col], sc1 = sq_c[col + 1];
                unsigned u0 = quant_el(sra, sc0, acc[ms][ns][0]);
                unsigned u1 = quant_el(sra, sc1, acc[ms][ns][1]);
                unsigned u2 = quant_el(srb, sc0, acc[ms][ns][2]);
                unsigned u3 = quant_el(srb, sc1, acc[ms][ns][3]);
                *(uint32_t*)(sm + OFF_NUM + (ra * NSTR + col) * 2)       = u0 | (u1 << 16);
                *(uint32_t*)(sm + OFF_NUM + ((ra + 8) * NSTR + col) * 2) = u2 | (u3 << 16);
            }
        }
        __syncthreads();

        // ---- copy-out 32x256 u16 tile to gmem + integer rowsums ----
        {
            const int row = t >> 3, cbase = (t & 7) * 32;
            unsigned short* gdst = g_num +
                ((size_t)(b * NPTS + r0 + row) << 12) + col0 + cbase;
            int s = 0;
            #pragma unroll
            for (int j = 0; j < 4; j++) {
                uint4 v = *(const uint4*)(sm + OFF_NUM + (row * NSTR + cbase + j * 8) * 2);
                s += (int)(v.x & 0xFFFFu) + (int)(v.x >> 16);
                s += (int)(v.y & 0xFFFFu) + (int)(v.y >> 16);
                s += (int)(v.z & 0xFFFFu) + (int)(v.z >> 16);
                s += (int)(v.w & 0xFFFFu) + (int)(v.w >> 16);
                *(uint4*)(gdst + j * 8) = v;
            }
            s += __shfl_xor_sync(0xFFFFFFFFu, s, 1);
            s += __shfl_xor_sync(0xFFFFFFFFu, s, 2);
            s += __shfl_xor_sync(0xFFFFFFFFu, s, 4);
            if ((lane & 7) == 0) atomicAdd(&rsum[row], s);
        }
    }

    __syncthreads();
    if (t < 32)
        g_scale[b * NPTS + r0 + t] = INV_RENORM / (float)rsum[t];
}

// ===========================================================================
// Kernel 3: rescale u16 numerators -> float output.
// out = u * (INV_RENORM / rowsum) + 1e-6 * INV_RENORM
// ===========================================================================
__global__ __launch_bounds__(256) void rescale_kernel(float* __restrict__ out)
{
    const size_t idx = (size_t)blockIdx.x * 256 + threadIdx.x;  // 8,388,608 total
    const size_t row = idx >> 9;                                 // 512 uint4 per row
    const uint4 v = ((const uint4*)g_num)[idx];
    const float s = g_scale[row];
    const float bias = 1e-6f * INV_RENORM;
    float4 o0, o1;
    o0.x = fmaf((float)(v.x & 0xFFFFu), s, bias);
    o0.y = fmaf((float)(v.x >> 16),     s, bias);
    o0.z = fmaf((float)(v.y & 0xFFFFu), s, bias);
    o0.w = fmaf((float)(v.y >> 16),     s, bias);
    o1.x = fmaf((float)(v.z & 0xFFFFu), s, bias);
    o1.y = fmaf((float)(v.z >> 16),     s, bias);
    o1.z = fmaf((float)(v.w & 0xFFFFu), s, bias);
    o1.w = fmaf((float)(v.w >> 16),     s, bias);
    ((float4*)out)[idx * 2]     = o0;
    ((float4*)out)[idx * 2 + 1] = o1;
}

// ===========================================================================
extern "C" void kernel_launch(void* const* d_in, const int* in_sizes, int n_in,
                              void* d_out, int out_size)
{
    const float* emb = (const float*)d_in[0];
    const float* W1  = (const float*)d_in[1];
    const float* b1  = (const float*)d_in[2];
    const float* W2  = (const float*)d_in[3];
    const float* b2  = (const float*)d_in[4];
    const float* W3  = (const float*)d_in[5];
    const float* b3  = (const float*)d_in[6];
    float* out = (float*)d_out;

    cudaFuncSetAttribute(gram_kernel, cudaFuncAttributeMaxDynamicSharedMemorySize, GRAM_SMEM);

    mlp_kernel<<<1024, 256>>>(emb, W1, b1, W2, b2, W3, b3);
    gram_kernel<<<512, 256, GRAM_SMEM>>>();
    rescale_kernel<<<32768, 256>>>(out);
}

// round 6
// speedup vs baseline: 1.8745x; 1.2844x over previous
#include <cuda_runtime.h>
#include <cuda_bf16.h>
#include <cstdint>

#define NPTS 4096
#define NROWS_TOT 16384
#define INV_RENORM (1.0f / 1.004096f)
#define NEG_HALF_L2E (-0.72134752f)
#define L2E (1.44269504f)

// degree-4 Chebyshev poly of 24000*exp(x) on [0,1], abs err ~1 count
#define PA0 24000.62f
#define PA1 23969.11f
#define PA2 12239.55f
#define PA3 3359.48f
#define PA4 1669.28f

// smem strides (elements)
#define ASTR 72
#define BSTR 72
#define NSTR 264

// ---- device-global scratch (no allocation allowed) ----
__device__ __align__(16) unsigned short g_zhi[NROWS_TOT * 64];
__device__ __align__(16) unsigned short g_zlo[NROWS_TOT * 64];
__device__ __align__(16) float          g_sq [NROWS_TOT];      // pre-scaled by -0.72135
__device__ __align__(16) unsigned short g_num[(size_t)NROWS_TOT * NPTS]; // 134MB
__device__ __align__(16) float          g_scale[NROWS_TOT];

// ===========================================================================
// Kernel 1: MLP 256 -> 128 -> 64 -> 50, bf16 split output + scaled sq norms.
// 32 rows/CTA, 512 threads, grid 512. Dynamic smem 64000 B.
// ===========================================================================
#define MLP_SMEM 64000

__global__ __launch_bounds__(512) void mlp_kernel(
    const float* __restrict__ emb,
    const float* __restrict__ W1, const float* __restrict__ b1,
    const float* __restrict__ W2, const float* __restrict__ b2,
    const float* __restrict__ W3, const float* __restrict__ b3)
{
    extern __shared__ char msm[];
    float (*E_s)[256]  = (float(*)[256])(msm);
    float (*h1_s)[128] = (float(*)[128])(msm + 32768);
    float (*h2_s)[64]  = (float(*)[64]) (msm + 49152);
    float (*z_s)[52]   = (float(*)[52]) (msm + 57344);

    const int t = threadIdx.x;
    const size_t rowbase = (size_t)blockIdx.x * 32;

    {
        const float4* src = (const float4*)(emb + rowbase * 256);
        float4* dst = (float4*)&E_s[0][0];
        #pragma unroll
        for (int i = 0; i < 4; i++) dst[t + i * 512] = src[t + i * 512];
    }
    __syncthreads();

    // layer 1: 256 -> 128, relu.  f = t&127, 4 row groups of 8.
    {
        const int f = t & 127, rg = (t >> 7) * 8;
        float acc[8];
        #pragma unroll
        for (int r = 0; r < 8; r++) acc[r] = 0.f;
        const float* w = W1 + f;
        #pragma unroll 2
        for (int d = 0; d < 256; d += 4) {
            float w0 = w[(d + 0) * 128], w1 = w[(d + 1) * 128];
            float w2 = w[(d + 2) * 128], w3 = w[(d + 3) * 128];
            #pragma unroll
            for (int r = 0; r < 8; r++) {
                float4 e = *(const float4*)&E_s[rg + r][d];
                acc[r] = fmaf(e.x, w0, acc[r]); acc[r] = fmaf(e.y, w1, acc[r]);
                acc[r] = fmaf(e.z, w2, acc[r]); acc[r] = fmaf(e.w, w3, acc[r]);
            }
        }
        const float bb = b1[f];
        #pragma unroll
        for (int r = 0; r < 8; r++) h1_s[rg + r][f] = fmaxf(acc[r] + bb, 0.f);
    }
    __syncthreads();

    // layer 2: 128 -> 64, relu.  f = t&63, 8 row groups of 4.
    {
        const int f = t & 63, rg = (t >> 6) * 4;
        float acc[4] = {0.f, 0.f, 0.f, 0.f};
        const float* w = W2 + f;
        #pragma unroll 2
        for (int d = 0; d < 128; d += 4) {
            float w0 = w[(d + 0) * 64], w1 = w[(d + 1) * 64];
            float w2 = w[(d + 2) * 64], w3 = w[(d + 3) * 64];
            #pragma unroll
            for (int r = 0; r < 4; r++) {
                float4 e = *(const float4*)&h1_s[rg + r][d];
                acc[r] = fmaf(e.x, w0, acc[r]); acc[r] = fmaf(e.y, w1, acc[r]);
                acc[r] = fmaf(e.z, w2, acc[r]); acc[r] = fmaf(e.w, w3, acc[r]);
            }
        }
        const float bb = b2[f];
        #pragma unroll
        for (int r = 0; r < 4; r++) h2_s[rg + r][f] = fmaxf(acc[r] + bb, 0.f);
    }
    __syncthreads();

    // layer 3: 64 -> 50
    {
        const int f = t & 63, rg = (t >> 6) * 4;
        if (f < 50) {
            float acc[4] = {0.f, 0.f, 0.f, 0.f};
            const float* w = W3 + f;
            #pragma unroll
            for (int d = 0; d < 64; d += 4) {
                float w0 = w[(d + 0) * 50], w1 = w[(d + 1) * 50];
                float w2 = w[(d + 2) * 50], w3 = w[(d + 3) * 50];
                #pragma unroll
                for (int r = 0; r < 4; r++) {
                    float4 e = *(const float4*)&h2_s[rg + r][d];
                    acc[r] = fmaf(e.x, w0, acc[r]); acc[r] = fmaf(e.y, w1, acc[r]);
                    acc[r] = fmaf(e.z, w2, acc[r]); acc[r] = fmaf(e.w, w3, acc[r]);
                }
            }
            const float bb = b3[f];
            #pragma unroll
            for (int r = 0; r < 4; r++) z_s[rg + r][f] = acc[r] + bb;
        }
    }
    __syncthreads();

    // bf16 split write: row = t>>4, k0 = (t&15)*4, pad K 50->64 with zeros
    {
        const int row = t >> 4, k0 = (t & 15) * 4;
        ushort4 hi4, lo4;
        unsigned short* hp = &hi4.x;
        unsigned short* lp = &lo4.x;
        #pragma unroll
        for (int j = 0; j < 4; j++) {
            const int k = k0 + j;
            float v = (k < 50) ? z_s[row][k] : 0.f;
            __nv_bfloat16 h = __float2bfloat16(v);
            float hf = __bfloat162float(h);
            __nv_bfloat16 l = __float2bfloat16(v - hf);
            hp[j] = __bfloat16_as_ushort(h);
            lp[j] = __bfloat16_as_ushort(l);
        }
        const size_t base = ((rowbase + row) << 6) + k0;
        *(ushort4*)(g_zhi + base) = hi4;
        *(ushort4*)(g_zlo + base) = lo4;
    }
    // squared norms, pre-scaled by -log2e/2 (sequential, deterministic)
    if (t < 32) {
        float s2 = 0.f;
        #pragma unroll
        for (int k = 0; k < 50; k++) s2 = fmaf(z_s[t][k], z_s[t][k], s2);
        g_sq[rowbase + t] = NEG_HALF_L2E * s2;
    }
}

// ===========================================================================
// Kernel 2: tensor-core gram + fused exp2/poly epilogue + u16 quantize +
// exact integer rowsums. CTA = 32 rows x 4096 cols, 256 threads (8 warps).
// ===========================================================================
#define OFF_BHI 0
#define OFF_BLO 36864
#define OFF_AHI 73728
#define OFF_ALO 78336
#define OFF_NUM 82944
#define OFF_SQC 99840
#define OFF_SQR 100864
#define OFF_RSUM 100992
#define GRAM_SMEM 101120

__device__ __forceinline__ void ldsm_x4(uint32_t addr, uint32_t* r) {
    asm volatile("ldmatrix.sync.aligned.m8n8.x4.shared.b16 {%0,%1,%2,%3}, [%4];"
                 : "=r"(r[0]), "=r"(r[1]), "=r"(r[2]), "=r"(r[3]) : "r"(addr));
}
__device__ __forceinline__ void mma_bf16(float* d, const uint32_t* a, const uint32_t* b) {
    asm volatile(
        "mma.sync.aligned.m16n8k16.row.col.f32.bf16.bf16.f32 "
        "{%0,%1,%2,%3},{%4,%5,%6,%7},{%8,%9},{%0,%1,%2,%3};"
        : "+f"(d[0]), "+f"(d[1]), "+f"(d[2]), "+f"(d[3])
        : "r"(a[0]), "r"(a[1]), "r"(a[2]), "r"(a[3]), "r"(b[0]), "r"(b[1]));
}
__device__ __forceinline__ void cp16(uint32_t dst, const void* src) {
    asm volatile("cp.async.cg.shared.global [%0], [%1], 16;" :: "r"(dst), "l"(src));
}
__device__ __forceinline__ void cp4(uint32_t dst, const void* src) {
    asm volatile("cp.async.ca.shared.global [%0], [%1], 4;" :: "r"(dst), "l"(src));
}
__device__ __forceinline__ void cp_commit() { asm volatile("cp.async.commit_group;"); }
__device__ __forceinline__ void cp_wait()   { asm volatile("cp.async.wait_group 0;"); }

// arg = sqp_r + sqp_c + log2e*dot  (= -d/(2 sigma^2) * log2e);  k = 2^arg;
// u = round(24000 * e^k) via degree-4 poly
__device__ __forceinline__ unsigned qexp(float arg) {
    float k;
    asm("ex2.approx.ftz.f32 %0, %1;" : "=f"(k) : "f"(arg));
    float p = fmaf(k, PA4, PA3);
    p = fmaf(k, p, PA2);
    p = fmaf(k, p, PA1);
    p = fmaf(k, p, PA0);
    return __float2uint_rn(p);
}

__global__ __launch_bounds__(256, 2) void gram_kernel()
{
    extern __shared__ char sm[];
    uint32_t smu;
    asm("{ .reg .u64 tt; cvta.to.shared.u64 tt, %1; cvt.u32.u64 %0, tt; }"
        : "=r"(smu) : "l"(sm));

    float* sqp_c = (float*)(sm + OFF_SQC);
    float* sqp_r = (float*)(sm + OFF_SQR);
    int*   rsum  = (int*)  (sm + OFF_RSUM);

    const int t    = threadIdx.x;
    const int lane = t & 31, warp = t >> 5;
    const int b    = blockIdx.x >> 7;
    const int r0   = (blockIdx.x & 127) * 32;
    const int gr   = lane >> 2;

    // ---- load A (32 rows, hi+lo) + sqp_r + init rowsum ----
    {
        const int row = t >> 3, seg = t & 7;
        const size_t src = ((size_t)(b * NPTS + r0 + row) << 6) + seg * 8;
        const int dsto = (row * ASTR + seg * 8) * 2;
        *(uint4*)(sm + OFF_AHI + dsto) = *(const uint4*)(g_zhi + src);
        *(uint4*)(sm + OFF_ALO + dsto) = *(const uint4*)(g_zlo + src);
    }
    if (t < 32) { sqp_r[t] = g_sq[b * NPTS + r0 + t]; rsum[t] = 0; }

    // ---- prologue: issue cp.async for tile 0 ----
    {
        const int row = t >> 3, seg = t & 7;
        #pragma unroll
        for (int i = 0; i < 8; i++) {
            const int rr = row + i * 32;
            const size_t src = ((size_t)(b * NPTS + rr) << 6) + seg * 8;
            const uint32_t dsto = (rr * BSTR + seg * 8) * 2;
            cp16(smu + OFF_BHI + dsto, g_zhi + src);
            cp16(smu + OFF_BLO + dsto, g_zlo + src);
        }
        cp4(smu + OFF_SQC + t * 4, g_sq + b * NPTS + t);
        cp_commit();
    }

    // ldmatrix lane offsets
    const int a_lr = (lane & 7) + ((lane >> 3) & 1) * 8;
    const int a_lc = (lane >> 4) * 8;
    const int b_lr = warp * 32 + (lane & 7) + ((lane >> 4) & 1) * 8;
    const int b_lc = ((lane >> 3) & 1) * 8;

    for (int tile = 0; tile < 16; tile++) {
        const int col0 = tile * 256;
        cp_wait();
        __syncthreads();   // B[tile] + sqp_c ready; prev copy-out done

        // ---- mma: per k-step load frags once, do 3 split terms ----
        float acc[2][4][4];
        #pragma unroll
        for (int ms = 0; ms < 2; ms++)
            #pragma unroll
            for (int ns = 0; ns < 4; ns++)
                #pragma unroll
                for (int q = 0; q < 4; q++) acc[ms][ns][q] = 0.f;

        #pragma unroll
        for (int ks = 0; ks < 4; ks++) {
            const int kk = ks * 16;
            uint32_t afh[2][4], afl[2][4], bfh[2][4], bfl[2][4];
            #pragma unroll
            for (int ms = 0; ms < 2; ms++) {
                const uint32_t ao = (((ms * 16 + a_lr) * ASTR) + kk + a_lc) * 2;
                ldsm_x4(smu + OFF_AHI + ao, afh[ms]);
                ldsm_x4(smu + OFF_ALO + ao, afl[ms]);
            }
            #pragma unroll
            for (int np = 0; np < 2; np++) {
                const uint32_t bo = (((b_lr + np * 16) * BSTR) + kk + b_lc) * 2;
                ldsm_x4(smu + OFF_BHI + bo, bfh[np]);
                ldsm_x4(smu + OFF_BLO + bo, bfl[np]);
            }
            #pragma unroll
            for (int ms = 0; ms < 2; ms++)
                #pragma unroll
                for (int np = 0; np < 2; np++) {
                    mma_bf16(acc[ms][np * 2],     afh[ms], &bfh[np][0]);
                    mma_bf16(acc[ms][np * 2 + 1], afh[ms], &bfh[np][2]);
                    mma_bf16(acc[ms][np * 2],     afh[ms], &bfl[np][0]);
                    mma_bf16(acc[ms][np * 2 + 1], afh[ms], &bfl[np][2]);
                    mma_bf16(acc[ms][np * 2],     afl[ms], &bfh[np][0]);
                    mma_bf16(acc[ms][np * 2 + 1], afl[ms], &bfh[np][2]);
                }
        }

        // ---- epilogue: 1 MUFU + deg-4 poly -> u16, stage to smem ----
        #pragma unroll
        for (int ms = 0; ms < 2; ms++) {
            const int ra = ms * 16 + gr;
            const float rr0 = sqp_r[ra], rr1 = sqp_r[ra + 8];
            #pragma unroll
            for (int ns = 0; ns < 4; ns++) {
                const int col = warp * 32 + ns * 8 + (lane & 3) * 2;
                const float sc0 = sqp_c[col], sc1 = sqp_c[col + 1];
                unsigned u0 = qexp(fmaf(L2E, acc[ms][ns][0], rr0 + sc0));
                unsigned u1 = qexp(fmaf(L2E, acc[ms][ns][1], rr0 + sc1));
                unsigned u2 = qexp(fmaf(L2E, acc[ms][ns][2], rr1 + sc0));
                unsigned u3 = qexp(fmaf(L2E, acc[ms][ns][3], rr1 + sc1));
                *(uint32_t*)(sm + OFF_NUM + (ra * NSTR + col) * 2)       = u0 | (u1 << 16);
                *(uint32_t*)(sm + OFF_NUM + ((ra + 8) * NSTR + col) * 2) = u2 | (u3 << 16);
            }
        }
        __syncthreads();   // staging done; all mma reads of B done

        // ---- issue next tile's loads (overlap with copy-out) ----
        if (tile < 15) {
            const int row = t >> 3, seg = t & 7;
            #pragma unroll
            for (int i = 0; i < 8; i++) {
                const int rr = row + i * 32;
                const size_t src = ((size_t)(b * NPTS + col0 + 256 + rr) << 6) + seg * 8;
                const uint32_t dsto = (rr * BSTR + seg * 8) * 2;
                cp16(smu + OFF_BHI + dsto, g_zhi + src);
                cp16(smu + OFF_BLO + dsto, g_zlo + src);
            }
            cp4(smu + OFF_SQC + t * 4, g_sq + b * NPTS + col0 + 256 + t);
        }
        cp_commit();

        // ---- copy-out 32x256 u16 tile to gmem + integer rowsums ----
        {
            const int row = t >> 3, cbase = (t & 7) * 32;
            unsigned short* gdst = g_num +
                ((size_t)(b * NPTS + r0 + row) << 12) + col0 + cbase;
            int s = 0;
            #pragma unroll
            for (int j = 0; j < 4; j++) {
                uint4 v = *(const uint4*)(sm + OFF_NUM + (row * NSTR + cbase + j * 8) * 2);
                s += (int)(v.x & 0xFFFFu) + (int)(v.x >> 16);
                s += (int)(v.y & 0xFFFFu) + (int)(v.y >> 16);
                s += (int)(v.z & 0xFFFFu) + (int)(v.z >> 16);
                s += (int)(v.w & 0xFFFFu) + (int)(v.w >> 16);
                *(uint4*)(gdst + j * 8) = v;
            }
            s += __shfl_xor_sync(0xFFFFFFFFu, s, 1);
            s += __shfl_xor_sync(0xFFFFFFFFu, s, 2);
            s += __shfl_xor_sync(0xFFFFFFFFu, s, 4);
            if ((lane & 7) == 0) atomicAdd(&rsum[row], s);
        }
    }

    __syncthreads();
    if (t < 32)
        g_scale[b * NPTS + r0 + t] = INV_RENORM / (float)rsum[t];
}

// ===========================================================================
// Kernel 3: rescale u16 numerators -> float output.
// ===========================================================================
__global__ __launch_bounds__(256) void rescale_kernel(float* __restrict__ out)
{
    const size_t idx = (size_t)blockIdx.x * 256 + threadIdx.x;  // 8,388,608 total
    const size_t row = idx >> 9;                                 // 512 uint4 per row
    const uint4 v = ((const uint4*)g_num)[idx];
    const float s = g_scale[row];
    const float bias = 1e-6f * INV_RENORM;
    float4 o0, o1;
    o0.x = fmaf((float)(v.x & 0xFFFFu), s, bias);
    o0.y = fmaf((float)(v.x >> 16),     s, bias);
    o0.z = fmaf((float)(v.y & 0xFFFFu), s, bias);
    o0.w = fmaf((float)(v.y >> 16),     s, bias);
    o1.x = fmaf((float)(v.z & 0xFFFFu), s, bias);
    o1.y = fmaf((float)(v.z >> 16),     s, bias);
    o1.z = fmaf((float)(v.w & 0xFFFFu), s, bias);
    o1.w = fmaf((float)(v.w >> 16),     s, bias);
    ((float4*)out)[idx * 2]     = o0;
    ((float4*)out)[idx * 2 + 1] = o1;
}

// ===========================================================================
extern "C" void kernel_launch(void* const* d_in, const int* in_sizes, int n_in,
                              void* d_out, int out_size)
{
    const float* emb = (const float*)d_in[0];
    const float* W1  = (const float*)d_in[1];
    const float* b1  = (const float*)d_in[2];
    const float* W2  = (const float*)d_in[3];
    const float* b2  = (const float*)d_in[4];
    const float* W3  = (const float*)d_in[5];
    const float* b3  = (const float*)d_in[6];
    float* out = (float*)d_out;

    cudaFuncSetAttribute(mlp_kernel,  cudaFuncAttributeMaxDynamicSharedMemorySize, MLP_SMEM);
    cudaFuncSetAttribute(gram_kernel, cudaFuncAttributeMaxDynamicSharedMemorySize, GRAM_SMEM);

    mlp_kernel<<<512, 512, MLP_SMEM>>>(emb, W1, b1, W2, b2, W3, b3);
    gram_kernel<<<512, 256, GRAM_SMEM>>>();
    rescale_kernel<<<32768, 256>>>(out);
}